// round 6
// baseline (speedup 1.0000x reference)
#include <cuda_runtime.h>
#include <cstdint>

constexpr int BS   = 16;
constexpr int Q    = 1024;
constexpr int NCLS = 91;
constexpr int T    = 128;
constexpr float COST_BBOX = 5.0f;

constexpr int WARPS          = 8;
constexpr int THREADS        = WARPS * 32;
constexpr int ROWS_PER_WARP  = 4;
constexpr int ROWS_PER_BLOCK = WARPS * ROWS_PER_WARP;   // 32

__global__ __launch_bounds__(THREADS)
void hungarian_cost_kernel(const float* __restrict__ logits,   // [BS,Q,NCLS]
                           const float* __restrict__ pboxes,   // [BS,Q,4]
                           const int*   __restrict__ labraw,   // [BS,T] int32 OR int64(LE)
                           const float* __restrict__ tboxes,   // [BS,T,4]
                           float* __restrict__ out)            // [BS,Q,T]
{
    __shared__ int    s_is64;
    __shared__ alignas(16) int s_lab[T];               // 16B-aligned for int4 reads
    __shared__ float4 s_tb[T];
    __shared__ float  s_exp[ROWS_PER_BLOCK][NCLS + 1];  // 32 x 92, +1 pad

    const int b    = blockIdx.y;
    const int tid  = threadIdx.x;
    const int warp = tid >> 5;
    const int lane = tid & 31;

    // ---- label layout probe (words [0,256) in-bounds for both layouts) ----
    if (warp == 0) {
        int bad = 0;
        #pragma unroll
        for (int j = 0; j < 4; ++j) {
            int idx  = lane * 4 + j;               // 0..127
            int even = labraw[2 * idx];
            int odd  = labraw[2 * idx + 1];
            bad |= (odd != 0) | (even < 0) | (even >= NCLS);
        }
        unsigned any = __ballot_sync(0xffffffffu, bad);
        if (lane == 0) s_is64 = (any == 0u);
    }
    __syncthreads();

    // ---- decode this batch's targets into shared ----
    if (tid < T) {
        const bool is64 = (s_is64 != 0);
        int v = is64 ? labraw[2 * (b * T + tid)] : labraw[b * T + tid];
        s_lab[tid] = min(max(v, 0), NCLS - 1);
        s_tb[tid]  = reinterpret_cast<const float4*>(tboxes)[b * T + tid];
    }

    // ---- 4 q-rows per warp: batch ALL global loads up front (MLP ~16) ----
    const int qbase = blockIdx.x * ROWS_PER_BLOCK + warp * ROWS_PER_WARP;
    const float* lg = logits + ((size_t)b * Q + qbase) * NCLS;
    const bool tail = (lane < NCLS - 64);   // lane < 27

    float l0[ROWS_PER_WARP], l1[ROWS_PER_WARP], l2[ROWS_PER_WARP];
    float4 pb[ROWS_PER_WARP];
    #pragma unroll
    for (int r = 0; r < ROWS_PER_WARP; ++r) {
        l0[r] = lg[r * NCLS + lane];
        l1[r] = lg[r * NCLS + lane + 32];
        l2[r] = tail ? lg[r * NCLS + lane + 64] : 0.0f;
        pb[r] = reinterpret_cast<const float4*>(pboxes)[b * Q + qbase + r];
    }

    // unnormalized softmax (logits ~ N(0,1): no overflow risk)
    float inv[ROWS_PER_WARP];
    const int rbase = warp * ROWS_PER_WARP;
    float s[ROWS_PER_WARP];
    #pragma unroll
    for (int r = 0; r < ROWS_PER_WARP; ++r) {
        l0[r] = __expf(l0[r]);
        l1[r] = __expf(l1[r]);
        l2[r] = tail ? __expf(l2[r]) : 0.0f;
        s[r] = l0[r] + l1[r] + l2[r];
    }
    #pragma unroll
    for (int o = 16; o > 0; o >>= 1) {
        #pragma unroll
        for (int r = 0; r < ROWS_PER_WARP; ++r)
            s[r] += __shfl_xor_sync(0xffffffffu, s[r], o);
    }
    #pragma unroll
    for (int r = 0; r < ROWS_PER_WARP; ++r) {
        inv[r] = __fdividef(1.0f, s[r]);
        s_exp[rbase + r][lane]      = l0[r];
        s_exp[rbase + r][lane + 32] = l1[r];
        if (tail) s_exp[rbase + r][lane + 64] = l2[r];
    }

    __syncthreads();   // targets ready; own s_exp writes ordered

    // ---- targets into registers: lane owns t = 4*lane + j, reused 32x ----
    const int4 lb = reinterpret_cast<const int4*>(s_lab)[lane];
    float4 tb[4];
    #pragma unroll
    for (int j = 0; j < 4; ++j) tb[j] = s_tb[4 * lane + j];
    const int lbj[4] = { lb.x, lb.y, lb.z, lb.w };

    // ---- emit 4 rows x 4 consecutive costs, STG.128 per row ----
    float* orow = out + ((size_t)b * Q + qbase) * T + 4 * lane;
    #pragma unroll
    for (int r = 0; r < ROWS_PER_WARP; ++r) {
        const float* er = s_exp[rbase + r];
        float4 res;
        float d;
        d = fabsf(pb[r].x - tb[0].x) + fabsf(pb[r].y - tb[0].y)
          + fabsf(pb[r].z - tb[0].z) + fabsf(pb[r].w - tb[0].w);
        res.x = COST_BBOX * d - er[lbj[0]] * inv[r];
        d = fabsf(pb[r].x - tb[1].x) + fabsf(pb[r].y - tb[1].y)
          + fabsf(pb[r].z - tb[1].z) + fabsf(pb[r].w - tb[1].w);
        res.y = COST_BBOX * d - er[lbj[1]] * inv[r];
        d = fabsf(pb[r].x - tb[2].x) + fabsf(pb[r].y - tb[2].y)
          + fabsf(pb[r].z - tb[2].z) + fabsf(pb[r].w - tb[2].w);
        res.z = COST_BBOX * d - er[lbj[2]] * inv[r];
        d = fabsf(pb[r].x - tb[3].x) + fabsf(pb[r].y - tb[3].y)
          + fabsf(pb[r].z - tb[3].z) + fabsf(pb[r].w - tb[3].w);
        res.w = COST_BBOX * d - er[lbj[3]] * inv[r];
        *reinterpret_cast<float4*>(orow + r * T) = res;
    }
}

extern "C" void kernel_launch(void* const* d_in, const int* in_sizes, int n_in,
                              void* d_out, int out_size)
{
    const float* logits = (const float*)d_in[0];   // [16,1024,91]
    const float* pboxes = (const float*)d_in[1];   // [16,1024,4]
    const int*   labraw = (const int*)d_in[2];     // [16,128] int32 or int64
    const float* tboxes = (const float*)d_in[3];   // [16,128,4]
    float* out = (float*)d_out;                    // [16,1024,128]

    dim3 grid(Q / ROWS_PER_BLOCK, BS);             // (32, 16) = 512 blocks
    hungarian_cost_kernel<<<grid, THREADS>>>(logits, pboxes, labraw, tboxes, out);
}